// round 5
// baseline (speedup 1.0000x reference)
#include <cuda_runtime.h>
#include <cstdint>

// ---- Problem constants -----------------------------------------------------
#define BB 16
#define NN 8192
#define NIN 4096
#define BN (BB * NN)          // 131072
#define KTOT (NN + NIN)       // 12288 virtual rows (W_int then W_ext)

#define ALPHA_F 0.9512294245007140f
#define ONE_MINUS_ALPHA_F (1.0f - 0.9512294245007140f)
#define RHO_A_F 0.9950124791926823f
#define BETA_F 1.8f
#define TH0_F 1.0f

// ---- Device scratch (static globals, allowed) ------------------------------
__device__ int g_list[BB][KTOT];
__device__ int g_cnt[BB];

// ---- Kernel 1: parallel per-batch active-row list --------------------------
__global__ __launch_bounds__(512)
void build_lists(const float* __restrict__ Xd,
                 const float* __restrict__ Xext) {
    int b = blockIdx.x;
    int tid = threadIdx.x;
    int w = tid >> 5;
    int lane = tid & 31;

    __shared__ int s_woff[16];
    __shared__ int s_total;

    const int base_k = w * (KTOT / 16);   // 768 rows per warp, 32-aligned

    float v[24];
#pragma unroll
    for (int u = 0; u < 24; u++) {
        int k = base_k + u * 32 + lane;
        if (k < NN)
            v[u] = Xd[((size_t)(7 * BB + b)) * NN + k];
        else
            v[u] = Xext[(size_t)b * NIN + (k - NN)];
    }

    unsigned m[24];
    int cnt = 0;
#pragma unroll
    for (int u = 0; u < 24; u++) {
        m[u] = __ballot_sync(0xffffffffu, v[u] > 0.5f);
        cnt += __popc(m[u]);
    }
    if (lane == 0) s_woff[w] = cnt;
    __syncthreads();

    if (w == 0 && lane < 16) {
        int val = s_woff[lane];
        int incl = val;
#pragma unroll
        for (int d = 1; d < 16; d <<= 1) {
            int o = __shfl_up_sync(0xffffu, incl, d, 16);
            if (lane >= d) incl += o;
        }
        s_woff[lane] = incl - val;
        if (lane == 15) s_total = incl;
    }
    __syncthreads();

    int pos = s_woff[w];
    int* list = g_list[b];
    unsigned lt = (1u << lane) - 1u;
#pragma unroll
    for (int u = 0; u < 24; u++) {
        if (v[u] > 0.5f)
            list[pos + __popc(m[u] & lt)] = base_k + u * 32 + lane;
        pos += __popc(m[u]);
    }
    if (tid == 0) g_cnt[b] = s_total;
}

// ---- Kernel 2: vectorized elementwise + delay-buffer shift -----------------
// out layout: X [0,BN) | V_new [BN,2BN) | a_new [2BN,3BN) | Xd_new [3BN,11BN)
__global__ __launch_bounds__(256)
void prep_elem(const float4* __restrict__ V4,
               const float4* __restrict__ a4,
               const float4* __restrict__ Xd4,
               float4* __restrict__ out4) {
    int i = blockIdx.x * blockDim.x + threadIdx.x;
    const int BN4 = BN / 4;
    if (i < BN4) {
        float4 Vv = V4[i];
        float4 av = a4[i];
        float4 x, an;
        x.x = (Vv.x >= TH0_F + BETA_F * av.x) ? 1.0f : 0.0f;
        x.y = (Vv.y >= TH0_F + BETA_F * av.y) ? 1.0f : 0.0f;
        x.z = (Vv.z >= TH0_F + BETA_F * av.z) ? 1.0f : 0.0f;
        x.w = (Vv.w >= TH0_F + BETA_F * av.w) ? 1.0f : 0.0f;
        an.x = RHO_A_F * av.x + x.x;
        an.y = RHO_A_F * av.y + x.y;
        an.z = RHO_A_F * av.z + x.z;
        an.w = RHO_A_F * av.w + x.w;
        out4[i] = x;               // X
        out4[2 * BN4 + i] = an;    // a_new
        out4[3 * BN4 + i] = x;     // Xd_new slot 0
    }
    if (i < 7 * BN4) {
        out4[4 * BN4 + i] = Xd4[i];  // Xd_new slots 1..7 = old slots 0..6
    }
}

// ---- Kernel 3: fused sparse row-sum + membrane epilogue --------------------
// grid (NN/128 col-tiles, BB batches); ONE warp per CTA, float4 per lane.
// List entries fetched cooperatively (32 at a time) and broadcast via shfl.
__global__ __launch_bounds__(32)
void spmm_kernel(const float* __restrict__ V,
                 const float* __restrict__ a,
                 const float* __restrict__ Wint,
                 const float* __restrict__ Wext,
                 float* __restrict__ out) {
    const int lane = threadIdx.x;
    const int b = blockIdx.y;
    const int j = blockIdx.x * 128 + lane * 4;

    const int cnt = g_cnt[b];
    const int* __restrict__ list = g_list[b];

    float4 acc = make_float4(0.f, 0.f, 0.f, 0.f);

    int i0 = 0;
    for (; i0 + 32 <= cnt; i0 += 32) {
        int k_my = list[i0 + lane];          // 32 row indices, one per lane
#pragma unroll
        for (int r = 0; r < 32; r += 8) {
            const float* p[8];
#pragma unroll
            for (int u = 0; u < 8; u++) {
                int k = __shfl_sync(0xffffffffu, k_my, r + u);
                p[u] = (k < NN) ? (Wint + ((size_t)k << 13))
                                : (Wext + ((size_t)(k - NN) << 13));
            }
            float4 wv[8];
#pragma unroll
            for (int u = 0; u < 8; u++) wv[u] = *(const float4*)(p[u] + j);
#pragma unroll
            for (int u = 0; u < 8; u++) {
                acc.x += wv[u].x; acc.y += wv[u].y;
                acc.z += wv[u].z; acc.w += wv[u].w;
            }
        }
    }
    // Tail (< 32 rows): shfl broadcast one row at a time
    {
        int rem = cnt - i0;
        int k_my = (lane < rem) ? list[i0 + lane] : 0;
        for (int r = 0; r < rem; r++) {
            int k = __shfl_sync(0xffffffffu, k_my, r);
            const float* p = (k < NN) ? (Wint + ((size_t)k << 13))
                                      : (Wext + ((size_t)(k - NN) << 13));
            float4 wv = *(const float4*)(p + j);
            acc.x += wv.x; acc.y += wv.y; acc.z += wv.z; acc.w += wv.w;
        }
    }

    // Fused membrane epilogue
    size_t idx = (size_t)b * NN + j;
    float4 Vv = *(const float4*)(V + idx);
    float4 av = *(const float4*)(a + idx);
    float4 vn;
    float x;
    x = (Vv.x >= TH0_F + BETA_F * av.x) ? 1.0f : 0.0f;
    vn.x = ALPHA_F * Vv.x * (1.0f - x) + ONE_MINUS_ALPHA_F * acc.x;
    x = (Vv.y >= TH0_F + BETA_F * av.y) ? 1.0f : 0.0f;
    vn.y = ALPHA_F * Vv.y * (1.0f - x) + ONE_MINUS_ALPHA_F * acc.y;
    x = (Vv.z >= TH0_F + BETA_F * av.z) ? 1.0f : 0.0f;
    vn.z = ALPHA_F * Vv.z * (1.0f - x) + ONE_MINUS_ALPHA_F * acc.z;
    x = (Vv.w >= TH0_F + BETA_F * av.w) ? 1.0f : 0.0f;
    vn.w = ALPHA_F * Vv.w * (1.0f - x) + ONE_MINUS_ALPHA_F * acc.w;

    *(float4*)(out + BN + idx) = vn;   // V_new region
}

// ---- Launch ----------------------------------------------------------------
extern "C" void kernel_launch(void* const* d_in, const int* in_sizes, int n_in,
                              void* d_out, int out_size) {
    const float* V    = (const float*)d_in[0];
    const float* a    = (const float*)d_in[1];
    const float* Xd   = (const float*)d_in[2];
    const float* Xext = (const float*)d_in[3];
    const float* Wint = (const float*)d_in[4];
    const float* Wext = (const float*)d_in[5];
    float* out = (float*)d_out;

    build_lists<<<BB, 512>>>(Xd, Xext);

    int total4 = 7 * BN / 4;
    prep_elem<<<(total4 + 255) / 256, 256>>>(
        (const float4*)V, (const float4*)a, (const float4*)Xd, (float4*)out);

    dim3 grid(NN / 128, BB);
    spmm_kernel<<<grid, 32>>>(V, a, Wint, Wext, out);
}